// round 10
// baseline (speedup 1.0000x reference)
#include <cuda_runtime.h>
#include <cuda_bf16.h>
#include <cstdint>
#include <math.h>

#define B_      1024
#define H_      256
#define G3_     768
#define LPRE    60
#define LFWD    80
#define ML_     80
#define NBLK    148

// ---------------- static device scratch (no allocation) ----------------
__device__ float g_catpre64[LPRE * B_ * 64];
__device__ float g_Mf64[G3_ * 64];
__device__ float g_gibias[G3_];
__device__ float g_GIenc[LPRE * B_ * G3_];
__device__ float g_ENC[LPRE * B_ * H_];
__device__ float g_M1[H_ * H_];
__device__ float g_c1[H_];
__device__ float g_c0fix[H_];
__device__ float g_Xe[LFWD * B_ * H_];
__device__ float g_Wstack[2 * G3_ * H_];
__device__ float g_bstack[2 * G3_];
__device__ float g_ctx[B_ * H_];
__device__ float g_logits[B_ * 128];
__device__ float g_g[B_ * H_];
__device__ float g_gigh[B_ * 2 * G3_];
__device__ float g_gh[B_ * G3_];
__device__ float g_hbuf[2][B_ * H_];
__device__ float g_Hall[LFWD * B_ * H_];
__device__ float g_We_pad[128 * H_];
__device__ float g_Wh_pad[128 * H_];
__device__ float g_Wfuse[128 * H_];
__device__ float g_abias_pad[128];
__device__ float g_corr_l[128];
__device__ float g_Wck[H_ * 512];
__device__ float g_bias0c[H_];
__device__ float g_XL[LFWD * B_ * 128];
__device__ float g_XC[LFWD * B_ * H_];
__device__ unsigned g_barcnt;
__device__ unsigned g_bargen;

// ================= helpers =================
__device__ __forceinline__ uint32_t smem_u32(const void* p) {
    uint32_t a;
    asm("{ .reg .u64 t; cvta.to.shared.u64 t, %1; cvt.u32.u64 %0, t; }" : "=r"(a) : "l"(p));
    return a;
}

#define STS128(r0, r1, r2, r3, smem_addr) \
    asm volatile("st.shared.v4.b32 [%0], {%1, %2, %3, %4};" \
        :: "r"(smem_addr), "r"(r0), "r"(r1), "r"(r2), "r"(r3) : "memory")

#define LDSM4(r0, r1, r2, r3, addr) \
    asm volatile("ldmatrix.sync.aligned.m8n8.x4.shared.b16 {%0,%1,%2,%3}, [%4];" \
        : "=r"(r0), "=r"(r1), "=r"(r2), "=r"(r3) : "r"(addr))

#define MMA16816(d, a, b) \
    asm volatile("mma.sync.aligned.m16n8k16.row.col.f32.bf16.bf16.f32 " \
        "{%0,%1,%2,%3},{%4,%5,%6,%7},{%8,%9},{%0,%1,%2,%3};" \
        : "+f"((d)[0]), "+f"((d)[1]), "+f"((d)[2]), "+f"((d)[3]) \
        : "r"((a)[0]), "r"((a)[1]), "r"((a)[2]), "r"((a)[3]), "r"((b)[0]), "r"((b)[1]))

__device__ __forceinline__ void cvt_hl(float x, float y, uint32_t& h, uint32_t& l) {
    __nv_bfloat162 hb = __floats2bfloat162_rn(x, y);
    float rx = x - __low2float(hb);
    float ry = y - __high2float(hb);
    __nv_bfloat162 lb = __floats2bfloat162_rn(rx, ry);
    h = *reinterpret_cast<uint32_t*>(&hb);
    l = *reinterpret_cast<uint32_t*>(&lb);
}

__device__ __forceinline__ uint32_t swz(int r, int c) {
    return (uint32_t)(r * 64 + ((c ^ ((r >> 1) & 3)) << 4));
}

__device__ __forceinline__ void ldg16(const float* __restrict__ p, float* f) {
#pragma unroll
    for (int i = 0; i < 4; i++) {
        float4 v = *(const float4*)(p + 4 * i);
        f[4 * i + 0] = v.x; f[4 * i + 1] = v.y; f[4 * i + 2] = v.z; f[4 * i + 3] = v.w;
    }
}

// L2-only loads for mutable cross-SM data inside the persistent kernel
__device__ __forceinline__ void ldg16cg(const float* __restrict__ p, float* f) {
#pragma unroll
    for (int i = 0; i < 4; i++) {
        float4 v = __ldcg((const float4*)(p + 4 * i));
        f[4 * i + 0] = v.x; f[4 * i + 1] = v.y; f[4 * i + 2] = v.z; f[4 * i + 3] = v.w;
    }
}

__device__ __forceinline__ float sigm(float x) { return 1.f / (1.f + expf(-x)); }

__device__ __forceinline__ float gru1(float ir, float iz, float inn,
                                      float hr, float hz, float hn, float hp) {
    float r = sigm(ir + hr);
    float z = sigm(iz + hz);
    float n = tanhf(inn + r * hn);
    return (1.f - z) * n + z * hp;
}

__device__ __forceinline__ void sts_half(uint32_t sh, uint32_t sl, int row, int c0, const float* f) {
    uint32_t h[8], l[8];
#pragma unroll
    for (int i = 0; i < 8; i++) cvt_hl(f[2 * i], f[2 * i + 1], h[i], l[i]);
    uint32_t o0 = swz(row, c0), o1 = swz(row, c0 + 1);
    STS128(h[0], h[1], h[2], h[3], sh + o0);
    STS128(h[4], h[5], h[6], h[7], sh + o1);
    STS128(l[0], l[1], l[2], l[3], sl + o0);
    STS128(l[4], l[5], l[6], l[7], sl + o1);
}

// ---------------- grid barrier (two-counter generational) ----------------
__device__ __forceinline__ void gridbar() {
    __syncthreads();
    if (threadIdx.x == 0) {
        __threadfence();
        unsigned gen = atomicAdd(&g_bargen, 0u);
        unsigned arrived = atomicAdd(&g_barcnt, 1u);
        if (arrived == NBLK - 1) {
            atomicExch(&g_barcnt, 0u);
            __threadfence();
            atomicAdd(&g_bargen, 1u);
        } else {
            while (atomicAdd(&g_bargen, 0u) == gen) __nanosleep(64);
        }
        __threadfence();
    }
    __syncthreads();
}

// ================= BM=128 mma.sync bf16x3 GEMM (prework only) =============
#define MG_SMEM (2 * 32768)
#define OFF_AH 0u
#define OFF_AL 8192u
#define OFF_BH 16384u
#define OFF_BL 24576u

__global__ __launch_bounds__(256, 1) void mmagemm_kernel(
    const float* __restrict__ A0, int lda0,
    const float* __restrict__ W, int ldw,
    const float* __restrict__ bias,
    float* __restrict__ C, int ldc,
    int M, int N, int K)
{
    extern __shared__ char dsm[];
    uint32_t sb = smem_u32(dsm);
    int tid = threadIdx.x, lane = tid & 31, wid = tid >> 5;
    int bm = blockIdx.y * 128, bn = blockIdx.x * 128;
    int warpM = wid & 3, warpN = wid >> 2;

    int lrow = tid >> 1, lhalf = tid & 1;
    const float* rowA = A0 + (size_t)(bm + lrow) * lda0 + lhalf * 16;
    const float* bp = W + (size_t)(bn + lrow) * ldw + lhalf * 16;

    float acc[2][8][4];
#pragma unroll
    for (int i = 0; i < 2; i++)
#pragma unroll
        for (int j = 0; j < 8; j++)
#pragma unroll
            for (int q = 0; q < 4; q++) acc[i][j][q] = 0.f;

    float fa[16], fb[16];
    int nk = K >> 5;

    ldg16(rowA, fa);
    ldg16(bp, fb);
    sts_half(sb + OFF_AH, sb + OFF_AL, lrow, lhalf * 2, fa);
    sts_half(sb + OFF_BH, sb + OFF_BL, lrow, lhalf * 2, fb);
    __syncthreads();

    for (int i = 0; i < nk; i++) {
        if (i + 1 < nk) {
            ldg16(rowA + (i + 1) * 32, fa);
            ldg16(bp + (i + 1) * 32, fb);
        }
        uint32_t st = sb + (uint32_t)(i & 1) * 32768u;
#pragma unroll
        for (int ks = 0; ks < 2; ks++) {
            uint32_t ah[2][4], al[2][4], bh[8][2], bl[8][2];
#pragma unroll
            for (int mf = 0; mf < 2; mf++) {
                int r = warpM * 32 + mf * 16 + (lane & 15);
                int c = ks * 2 + (lane >> 4);
                uint32_t o = swz(r, c);
                LDSM4(ah[mf][0], ah[mf][1], ah[mf][2], ah[mf][3], st + OFF_AH + o);
                LDSM4(al[mf][0], al[mf][1], al[mf][2], al[mf][3], st + OFF_AL + o);
            }
#pragma unroll
            for (int p = 0; p < 4; p++) {
                int r = warpN * 64 + p * 16 + (lane & 7) + ((lane >> 4) << 3);
                int c = ks * 2 + ((lane >> 3) & 1);
                uint32_t o = swz(r, c);
                LDSM4(bh[2 * p][0], bh[2 * p][1], bh[2 * p + 1][0], bh[2 * p + 1][1], st + OFF_BH + o);
                LDSM4(bl[2 * p][0], bl[2 * p][1], bl[2 * p + 1][0], bl[2 * p + 1][1], st + OFF_BL + o);
            }
#pragma unroll
            for (int mf = 0; mf < 2; mf++)
#pragma unroll
                for (int nf = 0; nf < 8; nf++) {
                    MMA16816(acc[mf][nf], ah[mf], bh[nf]);
                    MMA16816(acc[mf][nf], ah[mf], bl[nf]);
                    MMA16816(acc[mf][nf], al[mf], bh[nf]);
                }
        }
        if (i + 1 < nk) {
            uint32_t st2 = sb + (uint32_t)((i + 1) & 1) * 32768u;
            sts_half(st2 + OFF_AH, st2 + OFF_AL, lrow, lhalf * 2, fa);
            sts_half(st2 + OFF_BH, st2 + OFF_BL, lrow, lhalf * 2, fb);
            __syncthreads();
        }
    }

#pragma unroll
    for (int mf = 0; mf < 2; mf++)
#pragma unroll
        for (int nf = 0; nf < 8; nf++) {
            int m0 = bm + warpM * 32 + mf * 16 + (lane >> 2);
            int n = bn + warpN * 64 + nf * 8 + (lane & 3) * 2;
            float b0 = 0.f, b1 = 0.f;
            if (bias) { b0 = bias[n]; b1 = bias[n + 1]; }
#pragma unroll
            for (int hh = 0; hh < 2; hh++) {
                int m = m0 + hh * 8;
                float2 vv = make_float2(acc[mf][nf][2 * hh] + b0, acc[mf][nf][2 * hh + 1] + b1);
                *(float2*)(C + (size_t)m * ldc + n) = vv;
            }
        }
}

// ================= device 64x128 tile GEMM (persistent; CG A-loads) =================
#define O64_AH 0u
#define O64_AL 4096u
#define O64_BH 8192u
#define O64_BL 16384u
#define SER_SMEM (2 * 24576)

__device__ void tile_gemm64(uint32_t sb, int bm, int bn,
    const float* __restrict__ A0, const float* __restrict__ A1, int splitN, int lda0,
    const float* __restrict__ Ak, int ksplit, int ldak,
    const float* __restrict__ W, int ldw,
    const float* __restrict__ bias,
    const float* __restrict__ addmat, int ldadd,
    float* __restrict__ C, int ldc, int K, int act)
{
    int tid = threadIdx.x, lane = tid & 31, wid = tid >> 5;
    const float* __restrict__ A = (bn < splitN) ? A0 : A1;
    int warpM = wid & 1, warpN = wid >> 1;

    int lrow = tid >> 1, lhalf = tid & 1;
    int arow = (tid & 127) >> 1;
    bool doA = tid < 128;
    const float* rowA = A + (size_t)(bm + arow) * lda0 + lhalf * 16;
    const float* rowAk = Ak ? Ak + (size_t)(bm + arow) * ldak + lhalf * 16 : nullptr;
    const float* bp = W + (size_t)(bn + lrow) * ldw + lhalf * 16;

    float acc[2][4][4];
#pragma unroll
    for (int i = 0; i < 2; i++)
#pragma unroll
        for (int j = 0; j < 4; j++)
#pragma unroll
            for (int q = 0; q < 4; q++) acc[i][j][q] = 0.f;

    float fa[16], fb[16];
    int nk = K >> 5;

    {
        ldg16(bp, fb);
        if (doA) {
            const float* ap0 = (0 < ksplit) ? rowA : rowAk;
            ldg16cg(ap0, fa);
        }
        sts_half(sb + O64_BH, sb + O64_BL, lrow, lhalf * 2, fb);
        if (doA) sts_half(sb + O64_AH, sb + O64_AL, arow, lhalf * 2, fa);
    }
    __syncthreads();

    for (int i = 0; i < nk; i++) {
        if (i + 1 < nk) {
            int kk = (i + 1) * 32;
            ldg16(bp + kk, fb);
            if (doA) {
                const float* apn = (kk < ksplit) ? (rowA + kk) : (rowAk + (kk - ksplit));
                ldg16cg(apn, fa);
            }
        }
        uint32_t st = sb + (uint32_t)(i & 1) * 24576u;
#pragma unroll
        for (int ks = 0; ks < 2; ks++) {
            uint32_t ah[2][4], al[2][4], bh[4][2], bl[4][2];
#pragma unroll
            for (int mf = 0; mf < 2; mf++) {
                int r = warpM * 32 + mf * 16 + (lane & 15);
                int c = ks * 2 + (lane >> 4);
                uint32_t o = swz(r, c);
                LDSM4(ah[mf][0], ah[mf][1], ah[mf][2], ah[mf][3], st + O64_AH + o);
                LDSM4(al[mf][0], al[mf][1], al[mf][2], al[mf][3], st + O64_AL + o);
            }
#pragma unroll
            for (int p = 0; p < 2; p++) {
                int r = warpN * 32 + p * 16 + (lane & 7) + ((lane >> 4) << 3);
                int c = ks * 2 + ((lane >> 3) & 1);
                uint32_t o = swz(r, c);
                LDSM4(bh[2 * p][0], bh[2 * p][1], bh[2 * p + 1][0], bh[2 * p + 1][1], st + O64_BH + o);
                LDSM4(bl[2 * p][0], bl[2 * p][1], bl[2 * p + 1][0], bl[2 * p + 1][1], st + O64_BL + o);
            }
#pragma unroll
            for (int mf = 0; mf < 2; mf++)
#pragma unroll
                for (int nf = 0; nf < 4; nf++) {
                    MMA16816(acc[mf][nf], ah[mf], bh[nf]);
                    MMA16816(acc[mf][nf], ah[mf], bl[nf]);
                    MMA16816(acc[mf][nf], al[mf], bh[nf]);
                }
        }
        if (i + 1 < nk) {
            uint32_t st2 = sb + (uint32_t)((i + 1) & 1) * 24576u;
            sts_half(st2 + O64_BH, st2 + O64_BL, lrow, lhalf * 2, fb);
            if (doA) sts_half(st2 + O64_AH, st2 + O64_AL, arow, lhalf * 2, fa);
            __syncthreads();
        }
    }

#pragma unroll
    for (int mf = 0; mf < 2; mf++)
#pragma unroll
        for (int nf = 0; nf < 4; nf++) {
            int m0 = bm + warpM * 32 + mf * 16 + (lane >> 2);
            int n = bn + warpN * 32 + nf * 8 + (lane & 3) * 2;
            float b0 = 0.f, b1 = 0.f;
            if (bias) { b0 = bias[n]; b1 = bias[n + 1]; }
#pragma unroll
            for (int hh = 0; hh < 2; hh++) {
                int m = m0 + hh * 8;
                float v0 = acc[mf][nf][2 * hh] + b0;
                float v1 = acc[mf][nf][2 * hh + 1] + b1;
                if (addmat) {
                    const float* am = addmat + (size_t)m * ldadd + n;
                    v0 += am[0]; v1 += am[1];
                }
                if (act == 1) { v0 = tanhf(v0); v1 = tanhf(v1); }
                float2 vv = make_float2(v0, v1);
                *(float2*)(C + (size_t)m * ldc + n) = vv;
            }
        }
    __syncthreads();   // smem reuse safety across tiles
}

// ---------------- device GRU gates (wide, CG reads) ----------------
__device__ void gates_dev(const float* __restrict__ gi, int ldgi,
                          const float* __restrict__ gh, int ldgh,
                          const float* __restrict__ h,
                          float* __restrict__ h2, float* __restrict__ out2)
{
    for (int idx = blockIdx.x * 256 + threadIdx.x; idx < B_ * 64; idx += NBLK * 256) {
        int b = idx >> 6;
        int j = (idx & 63) << 2;
        const float* gib = gi + (size_t)b * ldgi + j;
        const float* ghp = gh + (size_t)b * ldgh + j;
        float4 ir  = __ldcg((const float4*)gib);
        float4 iz  = __ldcg((const float4*)(gib + 256));
        float4 inn = __ldcg((const float4*)(gib + 512));
        float4 hr  = __ldcg((const float4*)ghp);
        float4 hz  = __ldcg((const float4*)(ghp + 256));
        float4 hn  = __ldcg((const float4*)(ghp + 512));
        float4 hp  = __ldcg((const float4*)(h + (size_t)b * 256 + j));
        float4 v;
        v.x = gru1(ir.x, iz.x, inn.x, hr.x, hz.x, hn.x, hp.x);
        v.y = gru1(ir.y, iz.y, inn.y, hr.y, hz.y, hn.y, hp.y);
        v.z = gru1(ir.z, iz.z, inn.z, hr.z, hz.z, hn.z, hp.z);
        v.w = gru1(ir.w, iz.w, inn.w, hr.w, hz.w, hn.w, hp.w);
        *(float4*)(h2 + (size_t)b * 256 + j) = v;
        *(float4*)(out2 + (size_t)b * 256 + j) = v;
    }
}

// ---------------- device softmax+ctx (block handles <=7 rows concurrently) -----------
__device__ void smctx_dev(float* __restrict__ saw2 /* [7][80] smem */)
{
    int tid = threadIdx.x;
    int bid = blockIdx.x;
    int nr = (B_ - bid + NBLK - 1) / NBLK;   // 6 or 7
    int w = tid >> 5, lane = tid & 31;
    if (w < nr) {
        int b = bid + w * NBLK;
        const float* lb = g_logits + (size_t)b * 128;
        float x0 = __ldcg(lb + lane), x1 = __ldcg(lb + lane + 32);
        float x2 = (lane < 16) ? __ldcg(lb + lane + 64) : -1e30f;
        float mx = fmaxf(x0, fmaxf(x1, x2));
#pragma unroll
        for (int o = 16; o; o >>= 1) mx = fmaxf(mx, __shfl_xor_sync(0xffffffffu, mx, o));
        float e0 = expf(x0 - mx), e1 = expf(x1 - mx);
        float e2 = (lane < 16) ? expf(x2 - mx) : 0.f;
        float s = e0 + e1 + e2;
#pragma unroll
        for (int o = 16; o; o >>= 1) s += __shfl_xor_sync(0xffffffffu, s, o);
        float inv = 1.f / s;
        saw2[w * ML_ + lane] = e0 * inv;
        saw2[w * ML_ + lane + 32] = e1 * inv;
        if (lane < 16) saw2[w * ML_ + lane + 64] = e2 * inv;
    }
    __syncthreads();

    float acc[7];
#pragma unroll
    for (int r = 0; r < 7; r++) acc[r] = 0.f;
    const float* encb = g_ENC + tid;
    for (int m = 0; m < LPRE; m++) {
        size_t moff = (size_t)m * B_ * 256;
#pragma unroll
        for (int r = 0; r < 7; r++) {
            if (r < nr)
                acc[r] += saw2[r * ML_ + m] * encb[moff + (size_t)(bid + r * NBLK) * 256];
        }
    }
#pragma unroll
    for (int r = 0; r < 7; r++)
        if (r < nr) g_ctx[(size_t)(bid + r * NBLK) * 256 + tid] = acc[r];
    __syncthreads();
}

// ================= persistent serial kernel =================
__global__ __launch_bounds__(256, 1) void serial_kernel(
    const float* __restrict__ encWhh, const float* __restrict__ encBhh,
    const float* __restrict__ combW, const float* __restrict__ combB)
{
    extern __shared__ char dsm[];
    __shared__ float saw2[7 * ML_];
    uint32_t sb = smem_u32(dsm);
    int bid = blockIdx.x;

    float* hb[2] = { g_hbuf[0], g_hbuf[1] };
    int cur = 0;

    // ---- encoder: 60 steps ----
    for (int t = 0; t < LPRE; t++) {
        const float* h = hb[cur];
        for (int tile = bid; tile < 96; tile += NBLK) {
            int bm = (tile & 15) * 64, bn = (tile >> 4) * 128;
            tile_gemm64(sb, bm, bn, h, h, 1 << 30, 256, nullptr, 1 << 30, 0,
                        encWhh, 256, encBhh, nullptr, 0, g_gh, G3_, 256, 0);
        }
        gridbar();
        gates_dev(g_GIenc + (size_t)t * B_ * G3_, G3_, g_gh, G3_,
                  h, hb[cur ^ 1], g_ENC + (size_t)t * B_ * H_);
        gridbar();
        cur ^= 1;
    }

    // ---- decoder: 80 steps ----
    for (int t = 0; t < LFWD; t++) {
        const float* h = hb[cur];
        // P1: logits = h @ Wl^T (+XL[t]) (+corr for t=0)
        if (t == 0) {
            for (int tile = bid; tile < 16; tile += NBLK)
                tile_gemm64(sb, tile * 64, 0, h, h, 1 << 30, 256, nullptr, 1 << 30, 0,
                            g_Wh_pad, 256, g_corr_l, g_XL, 128, g_logits, 128, 256, 0);
        } else {
            for (int tile = bid; tile < 16; tile += NBLK)
                tile_gemm64(sb, tile * 64, 0, h, h, 1 << 30, 256, nullptr, 1 << 30, 0,
                            g_Wfuse, 256, nullptr, g_XL + (size_t)t * B_ * 128, 128,
                            g_logits, 128, 256, 0);
        }
        gridbar();
        // P2: softmax + ctx
        smctx_dev(saw2);
        gridbar();
        // P3: g = tanh(...)
        if (t == 0) {
            for (int tile = bid; tile < 32; tile += NBLK) {
                int bm = (tile & 15) * 64, bn = (tile >> 4) * 128;
                tile_gemm64(sb, bm, bn, g_ctx, g_ctx, 1 << 30, 256, nullptr, 1 << 30, 0,
                            combW + 256, 512, g_bias0c, g_XC, 256, g_g, 256, 256, 1);
            }
        } else {
            for (int tile = bid; tile < 32; tile += NBLK) {
                int bm = (tile & 15) * 64, bn = (tile >> 4) * 128;
                tile_gemm64(sb, bm, bn, g_ctx, g_ctx, 1 << 30, 256, h, 256, 256,
                            g_Wck, 512, combB, g_XC + (size_t)t * B_ * 256, 256,
                            g_g, 256, 512, 1);
            }
        }
        gridbar();
        // P4: gigh = [g|h] @ Wstack
        for (int tile = bid; tile < 192; tile += NBLK) {
            int bm = (tile & 15) * 64, bn = (tile >> 4) * 128;
            tile_gemm64(sb, bm, bn, g_g, h, 768, 256, nullptr, 1 << 30, 0,
                        g_Wstack, 256, g_bstack, nullptr, 0, g_gigh, 1536, 256, 0);
        }
        gridbar();
        // P5: gates -> h(t+1), Hall[t]
        gates_dev(g_gigh, 1536, g_gigh + 768, 1536, h,
                  hb[cur ^ 1], g_Hall + (size_t)t * B_ * H_);
        gridbar();
        cur ^= 1;
    }
}

// ---------------- SIMT fp32 GEMM (final output) ----------------
__global__ __launch_bounds__(256) void gemm_kernel(
    const float* __restrict__ A, const float* __restrict__ W, int ldw,
    const float* __restrict__ bias,
    float* __restrict__ C, int ldc,
    int M, int N, int K)
{
    __shared__ float As[16][64];
    __shared__ float Bs[16][64];
    int bn = blockIdx.x * 64;
    int bm = blockIdx.y * 64;

    int tid = threadIdx.x;
    int tx = tid & 15, ty = tid >> 4;
    int lr = tid >> 2;
    int lk = (tid & 3) * 4;

    float acc[4][4];
#pragma unroll
    for (int i = 0; i < 4; i++)
#pragma unroll
        for (int j = 0; j < 4; j++) acc[i][j] = 0.f;

    for (int k0 = 0; k0 < K; k0 += 16) {
        float4 a4 = *(const float4*)(A + (size_t)(bm + lr) * K + k0 + lk);
        As[lk + 0][lr] = a4.x; As[lk + 1][lr] = a4.y;
        As[lk + 2][lr] = a4.z; As[lk + 3][lr] = a4.w;
        float4 b4 = make_float4(0.f, 0.f, 0.f, 0.f);
        if (bn + lr < N)
            b4 = *(const float4*)(W + (size_t)(bn + lr) * ldw + k0 + lk);
        Bs[lk + 0][lr] = b4.x; Bs[lk + 1][lr] = b4.y;
        Bs[lk + 2][lr] = b4.z; Bs[lk + 3][lr] = b4.w;
        __syncthreads();
#pragma unroll
        for (int kk = 0; kk < 16; kk++) {
            float ra[4], rb[4];
#pragma unroll
            for (int i = 0; i < 4; i++) ra[i] = As[kk][ty * 4 + i];
#pragma unroll
            for (int j = 0; j < 4; j++) rb[j] = Bs[kk][tx * 4 + j];
#pragma unroll
            for (int i = 0; i < 4; i++)
#pragma unroll
                for (int j = 0; j < 4; j++) acc[i][j] += ra[i] * rb[j];
        }
        __syncthreads();
    }

#pragma unroll
    for (int i = 0; i < 4; i++) {
        int m = bm + ty * 4 + i;
#pragma unroll
        for (int j = 0; j < 4; j++) {
            int n = bn + tx * 4 + j;
            if (n < N)
                C[(size_t)m * ldc + n] = acc[i][j] + bias[n];
        }
    }
}

// ---------------- prep kernels ----------------
__global__ void pack_catpre_kernel(const float* __restrict__ px, const float* __restrict__ py,
                                   float* __restrict__ out)
{
    int idx = blockIdx.x * 256 + threadIdx.x;
    if (idx >= LPRE * B_ * 64) return;
    int c = idx & 63;
    int tb = idx >> 6;
    float v = 0.f;
    if (c < 32) v = px[(size_t)tb * 32 + c];
    else if (c < 48) v = py[(size_t)tb * 16 + (c - 32)];
    out[idx] = v;
}

__global__ void make_Mf_kernel(const float* __restrict__ Wih, const float* __restrict__ embW,
                               const float* __restrict__ embb, const float* __restrict__ bih,
                               float* __restrict__ Mf, float* __restrict__ gib)
{
    int idx = blockIdx.x * 256 + threadIdx.x;
    if (idx < G3_ * 64) {
        int i = idx >> 6, k = idx & 63;
        float s = 0.f;
        if (k < 48)
            for (int j = 0; j < H_; j++) s += Wih[(size_t)i * H_ + j] * embW[(size_t)j * 48 + k];
        Mf[idx] = s;
    } else if (idx < G3_ * 64 + G3_) {
        int i = idx - G3_ * 64;
        float s = bih[i];
        for (int j = 0; j < H_; j++) s += Wih[(size_t)i * H_ + j] * embb[j];
        gib[i] = s;
    }
}

__global__ void make_M1_kernel(const float* __restrict__ decEmbW, const float* __restrict__ decEmbb,
                               const float* __restrict__ outW, const float* __restrict__ outb,
                               float* __restrict__ M1, float* __restrict__ c1, float* __restrict__ c0fix)
{
    int idx = blockIdx.x * 256 + threadIdx.x;
    if (idx < H_ * H_) {
        int i = idx / H_, j = idx % H_;
        float s = 0.f;
        for (int k = 0; k < 16; k++) s += decEmbW[(size_t)i * 48 + k] * outW[(size_t)k * H_ + j];
        M1[idx] = s;
    } else if (idx < H_ * H_ + H_) {
        int i = idx - H_ * H_;
        float s = 0.f;
        for (int k = 0; k < 16; k++) s += decEmbW[(size_t)i * 48 + k] * outb[k];
        c1[i] = s + decEmbb[i];
        c0fix[i] = -s;
    }
}

__global__ void stack_copy_kernel(const float* __restrict__ Wih, const float* __restrict__ Whh,
                                  const float* __restrict__ bih, const float* __restrict__ bhh,
                                  float* __restrict__ Wst, float* __restrict__ bst)
{
    int idx = blockIdx.x * 256 + threadIdx.x;
    if (idx < G3_ * H_) {
        Wst[idx] = Wih[idx];
        Wst[G3_ * H_ + idx] = Whh[idx];
    }
    if (idx < G3_) { bst[idx] = bih[idx]; bst[G3_ + idx] = bhh[idx]; }
}

__global__ void zero_h_kernel(float* __restrict__ h)
{
    int idx = blockIdx.x * 256 + threadIdx.x;
    if (idx < B_ * H_) h[idx] = 0.f;
}

__global__ void make_attnprep_kernel(const float* __restrict__ attnW, const float* __restrict__ attnb,
                                     const float* __restrict__ M1, const float* __restrict__ c0fix,
                                     float* __restrict__ We_pad, float* __restrict__ Wh_pad,
                                     float* __restrict__ Wfuse, float* __restrict__ abias_pad,
                                     float* __restrict__ corr_l)
{
    int idx = blockIdx.x * 256 + threadIdx.x;
    if (idx >= 128 * H_) return;
    int m = idx >> 8, k = idx & 255;
    float we = 0.f, wh = 0.f, wf = 0.f;
    if (m < ML_) {
        we = attnW[(size_t)m * 512 + k];
        wh = attnW[(size_t)m * 512 + 256 + k];
        float s = wh;
        for (int j = 0; j < H_; j++) s += attnW[(size_t)m * 512 + j] * M1[(size_t)j * H_ + k];
        wf = s;
    }
    We_pad[idx] = we; Wh_pad[idx] = wh; Wfuse[idx] = wf;
    if (k == 0) {
        float ab = 0.f, cl = 0.f;
        if (m < ML_) {
            ab = attnb[m];
            for (int j = 0; j < H_; j++) cl += c0fix[j] * attnW[(size_t)m * 512 + j];
        }
        abias_pad[m] = ab;
        corr_l[m] = cl;
    }
}

__global__ void make_wck_kernel(const float* __restrict__ combW, const float* __restrict__ combb,
                                const float* __restrict__ M1, const float* __restrict__ c0fix,
                                float* __restrict__ Wck, float* __restrict__ bias0c)
{
    int idx = blockIdx.x * 256 + threadIdx.x;
    if (idx >= H_ * 512) return;
    int n = idx >> 9, k = idx & 511;
    float v;
    if (k < 256) {
        v = combW[(size_t)n * 512 + 256 + k];
    } else {
        float s = 0.f;
        int kk = k - 256;
        for (int j = 0; j < H_; j++) s += combW[(size_t)n * 512 + j] * M1[(size_t)j * H_ + kk];
        v = s;
    }
    Wck[idx] = v;
    if (k == 0) {
        float s = combb[n];
        for (int j = 0; j < H_; j++) s += combW[(size_t)n * 512 + j] * c0fix[j];
        bias0c[n] = s;
    }
}

// ---------------- host launcher ----------------
static inline void run_mma(const float* A, int lda, const float* W, int ldw,
                           const float* bias, float* C, int ldc, int M, int N, int K)
{
    dim3 grid(N / 128, M / 128);
    mmagemm_kernel<<<grid, 256, MG_SMEM>>>(A, lda, W, ldw, bias, C, ldc, M, N, K);
}

extern "C" void kernel_launch(void* const* d_in, const int* in_sizes, int n_in,
                              void* d_out, int out_size)
{
    const float* pre_x    = (const float*)d_in[0];
    const float* pre_y    = (const float*)d_in[1];
    const float* fwd_x    = (const float*)d_in[2];
    const float* encEmbW  = (const float*)d_in[3];
    const float* encEmbB  = (const float*)d_in[4];
    const float* encWih   = (const float*)d_in[5];
    const float* encWhh   = (const float*)d_in[6];
    const float* encBih   = (const float*)d_in[7];
    const float* encBhh   = (const float*)d_in[8];
    const float* decEmbW  = (const float*)d_in[9];
    const float* decEmbB  = (const float*)d_in[10];
    const float* attnW    = (const float*)d_in[11];
    const float* attnB    = (const float*)d_in[12];
    const float* combW    = (const float*)d_in[13];
    const float* combB    = (const float*)d_in[14];
    const float* decWih   = (const float*)d_in[15];
    const float* decWhh   = (const float*)d_in[16];
    const float* decBih   = (const float*)d_in[17];
    const float* decBhh   = (const float*)d_in[18];
    const float* outW     = (const float*)d_in[19];
    const float* outB     = (const float*)d_in[20];
    float* out = (float*)d_out;

    cudaFuncSetAttribute(mmagemm_kernel, cudaFuncAttributeMaxDynamicSharedMemorySize, MG_SMEM);
    cudaFuncSetAttribute(serial_kernel, cudaFuncAttributeMaxDynamicSharedMemorySize, SER_SMEM);

    float *catpre, *Mf, *gibias, *GIenc, *M1, *c1, *c0fix, *Xe;
    float *Wstack, *bstack, *hb0, *Hall;
    float *We_pad, *Wh_pad, *Wfuse, *abias_pad, *corr_l, *Wck, *bias0c, *XL, *XC;
    cudaGetSymbolAddress((void**)&catpre, g_catpre64);
    cudaGetSymbolAddress((void**)&Mf, g_Mf64);
    cudaGetSymbolAddress((void**)&gibias, g_gibias);
    cudaGetSymbolAddress((void**)&GIenc, g_GIenc);
    cudaGetSymbolAddress((void**)&M1, g_M1);
    cudaGetSymbolAddress((void**)&c1, g_c1);
    cudaGetSymbolAddress((void**)&c0fix, g_c0fix);
    cudaGetSymbolAddress((void**)&Xe, g_Xe);
    cudaGetSymbolAddress((void**)&Wstack, g_Wstack);
    cudaGetSymbolAddress((void**)&bstack, g_bstack);
    cudaGetSymbolAddress((void**)&hb0, g_hbuf);
    cudaGetSymbolAddress((void**)&Hall, g_Hall);
    cudaGetSymbolAddress((void**)&We_pad, g_We_pad);
    cudaGetSymbolAddress((void**)&Wh_pad, g_Wh_pad);
    cudaGetSymbolAddress((void**)&Wfuse, g_Wfuse);
    cudaGetSymbolAddress((void**)&abias_pad, g_abias_pad);
    cudaGetSymbolAddress((void**)&corr_l, g_corr_l);
    cudaGetSymbolAddress((void**)&Wck, g_Wck);
    cudaGetSymbolAddress((void**)&bias0c, g_bias0c);
    cudaGetSymbolAddress((void**)&XL, g_XL);
    cudaGetSymbolAddress((void**)&XC, g_XC);

    // ---- prep ----
    pack_catpre_kernel<<<(LPRE * B_ * 64 + 255) / 256, 256>>>(pre_x, pre_y, catpre);
    make_Mf_kernel<<<(G3_ * 64 + G3_ + 255) / 256, 256>>>(encWih, encEmbW, encEmbB, encBih, Mf, gibias);
    make_M1_kernel<<<(H_ * H_ + H_ + 255) / 256, 256>>>(decEmbW, decEmbB, outW, outB, M1, c1, c0fix);
    stack_copy_kernel<<<(G3_ * H_ + 255) / 256, 256>>>(decWih, decWhh, decBih, decBhh, Wstack, bstack);
    zero_h_kernel<<<(B_ * H_ + 255) / 256, 256>>>(hb0);
    make_attnprep_kernel<<<(128 * H_ + 255) / 256, 256>>>(attnW, attnB, M1, c0fix,
                                                          We_pad, Wh_pad, Wfuse, abias_pad, corr_l);
    make_wck_kernel<<<(H_ * 512 + 255) / 256, 256>>>(combW, combB, M1, c0fix, Wck, bias0c);

    // ---- prework GEMMs (parallel over all steps) ----
    run_mma(catpre, 64, Mf, 64, gibias, GIenc, G3_, LPRE * B_, G3_, 64);
    {
        // Xe: K=32 -> use mma with lda 32 via BM=128 kernel
        dim3 grid(H_ / 128, (LFWD * B_) / 128);
        mmagemm_kernel<<<grid, 256, MG_SMEM>>>(fwd_x, 32, decEmbW + 16, 48, c1, Xe, H_, LFWD * B_, H_, 32);
    }
    run_mma(Xe, 256, We_pad, 256, abias_pad, XL, 128, LFWD * B_, 128, 256);
    run_mma(Xe, 256, combW, 512, nullptr, XC, 256, LFWD * B_, 256, 256);

    // ---- the whole serial chain: ONE persistent kernel ----
    serial_kernel<<<NBLK, 256, SER_SMEM>>>(encWhh, encBhh, combW, combB);

    // ---- final outputs: ys = Hall @ out_W.T + out_b ----
    {
        dim3 grid(1, (LFWD * B_) / 64);
        gemm_kernel<<<grid, 256>>>(Hall, outW, H_, outB, out, 16, LFWD * B_, 16, H_);
    }
}

// round 11
// speedup vs baseline: 1.5793x; 1.5793x over previous
#include <cuda_runtime.h>
#include <cuda_bf16.h>
#include <cstdint>
#include <math.h>

#define B_      1024
#define H_      256
#define G3_     768
#define LPRE    60
#define LFWD    80
#define ML_     80

// ---------------- static device scratch (no allocation) ----------------
__device__ float g_catpre64[LPRE * B_ * 64];
__device__ float g_Mf64[G3_ * 64];
__device__ float g_gibias[G3_];
__device__ float g_GIenc[LPRE * B_ * G3_];
__device__ float g_ENC[LPRE * B_ * H_];
__device__ float g_M1[H_ * H_];
__device__ float g_c1[H_];
__device__ float g_c0fix[H_];
__device__ float g_Xe[LFWD * B_ * H_];
__device__ float g_Wstack[2 * G3_ * H_];
__device__ float g_bstack[2 * G3_];
__device__ float g_ctx[B_ * H_];
__device__ float g_lp[B_ * 384];           // [logits(128) | pre(256)] per row
__device__ float g_g[B_ * H_];
__device__ float g_gigh[B_ * 2 * G3_];
__device__ float g_gh[B_ * G3_];
__device__ float g_hbuf[2][B_ * H_];
__device__ float g_Hall[LFWD * B_ * H_];
__device__ float g_Wh_pad[128 * H_];
__device__ float g_W2[384 * H_];           // rows 0-127: Wfuse, rows 128-383: Wch
__device__ float g_WexC[384 * H_];         // rows 0-127: We_pad, rows 128-383: combW_e
__device__ float g_bias384[384];           // [attn_b | comb_b]
__device__ float g_corr_l[128];
__device__ float g_corr_c[H_];             // combW_e . c0fix
__device__ float g_XLC[LFWD * B_ * 384];   // Xe@WexC^T + bias384

// ================= helpers =================
__device__ __forceinline__ uint32_t smem_u32(const void* p) {
    uint32_t a;
    asm("{ .reg .u64 t; cvta.to.shared.u64 t, %1; cvt.u32.u64 %0, t; }" : "=r"(a) : "l"(p));
    return a;
}

#define STS128(r0, r1, r2, r3, smem_addr) \
    asm volatile("st.shared.v4.b32 [%0], {%1, %2, %3, %4};" \
        :: "r"(smem_addr), "r"(r0), "r"(r1), "r"(r2), "r"(r3) : "memory")

#define LDSM4(r0, r1, r2, r3, addr) \
    asm volatile("ldmatrix.sync.aligned.m8n8.x4.shared.b16 {%0,%1,%2,%3}, [%4];" \
        : "=r"(r0), "=r"(r1), "=r"(r2), "=r"(r3) : "r"(addr))

#define MMA16816(d, a, b) \
    asm volatile("mma.sync.aligned.m16n8k16.row.col.f32.bf16.bf16.f32 " \
        "{%0,%1,%2,%3},{%4,%5,%6,%7},{%8,%9},{%0,%1,%2,%3};" \
        : "+f"((d)[0]), "+f"((d)[1]), "+f"((d)[2]), "+f"((d)[3]) \
        : "r"((a)[0]), "r"((a)[1]), "r"((a)[2]), "r"((a)[3]), "r"((b)[0]), "r"((b)[1]))

__device__ __forceinline__ void cvt_hl(float x, float y, uint32_t& h, uint32_t& l) {
    __nv_bfloat162 hb = __floats2bfloat162_rn(x, y);
    float rx = x - __low2float(hb);
    float ry = y - __high2float(hb);
    __nv_bfloat162 lb = __floats2bfloat162_rn(rx, ry);
    h = *reinterpret_cast<uint32_t*>(&hb);
    l = *reinterpret_cast<uint32_t*>(&lb);
}

__device__ __forceinline__ uint32_t swz(int r, int c) {
    return (uint32_t)(r * 64 + ((c ^ ((r >> 1) & 3)) << 4));
}

__device__ __forceinline__ void ldg16(const float* __restrict__ p, float* f) {
#pragma unroll
    for (int i = 0; i < 4; i++) {
        float4 v = *(const float4*)(p + 4 * i);
        f[4 * i + 0] = v.x; f[4 * i + 1] = v.y; f[4 * i + 2] = v.z; f[4 * i + 3] = v.w;
    }
}

__device__ __forceinline__ float sigm(float x) { return 1.f / (1.f + expf(-x)); }

__device__ __forceinline__ float gru1(float ir, float iz, float inn,
                                      float hr, float hz, float hn, float hp) {
    float r = sigm(ir + hr);
    float z = sigm(iz + hz);
    float n = tanhf(inn + r * hn);
    return (1.f - z) * n + z * hp;
}

__device__ __forceinline__ void sts_half(uint32_t sh, uint32_t sl, int row, int c0, const float* f) {
    uint32_t h[8], l[8];
#pragma unroll
    for (int i = 0; i < 8; i++) cvt_hl(f[2 * i], f[2 * i + 1], h[i], l[i]);
    uint32_t o0 = swz(row, c0), o1 = swz(row, c0 + 1);
    STS128(h[0], h[1], h[2], h[3], sh + o0);
    STS128(h[4], h[5], h[6], h[7], sh + o1);
    STS128(l[0], l[1], l[2], l[3], sl + o0);
    STS128(l[4], l[5], l[6], l[7], sl + o1);
}

// ================= BM=128 mma.sync bf16x3 GEMM (prework / gigh alt) =============
#define MG_SMEM (2 * 32768)
#define OFF_AH 0u
#define OFF_AL 8192u
#define OFF_BH 16384u
#define OFF_BL 24576u

__global__ __launch_bounds__(256, 1) void mmagemm_kernel(
    const float* __restrict__ A0, int lda0,
    const float* __restrict__ W, int ldw,
    const float* __restrict__ bias,
    float* __restrict__ C, int ldc,
    int M, int N, int K)
{
    extern __shared__ char dsm[];
    uint32_t sb = smem_u32(dsm);
    int tid = threadIdx.x, lane = tid & 31, wid = tid >> 5;
    int bm = blockIdx.y * 128, bn = blockIdx.x * 128;
    int warpM = wid & 3, warpN = wid >> 2;

    int lrow = tid >> 1, lhalf = tid & 1;
    const float* rowA = A0 + (size_t)(bm + lrow) * lda0 + lhalf * 16;
    const float* bp = W + (size_t)(bn + lrow) * ldw + lhalf * 16;

    float acc[2][8][4];
#pragma unroll
    for (int i = 0; i < 2; i++)
#pragma unroll
        for (int j = 0; j < 8; j++)
#pragma unroll
            for (int q = 0; q < 4; q++) acc[i][j][q] = 0.f;

    float fa[16], fb[16];
    int nk = K >> 5;

    ldg16(rowA, fa);
    ldg16(bp, fb);
    sts_half(sb + OFF_AH, sb + OFF_AL, lrow, lhalf * 2, fa);
    sts_half(sb + OFF_BH, sb + OFF_BL, lrow, lhalf * 2, fb);
    __syncthreads();

    for (int i = 0; i < nk; i++) {
        if (i + 1 < nk) {
            ldg16(rowA + (i + 1) * 32, fa);
            ldg16(bp + (i + 1) * 32, fb);
        }
        uint32_t st = sb + (uint32_t)(i & 1) * 32768u;
#pragma unroll
        for (int ks = 0; ks < 2; ks++) {
            uint32_t ah[2][4], al[2][4], bh[8][2], bl[8][2];
#pragma unroll
            for (int mf = 0; mf < 2; mf++) {
                int r = warpM * 32 + mf * 16 + (lane & 15);
                int c = ks * 2 + (lane >> 4);
                uint32_t o = swz(r, c);
                LDSM4(ah[mf][0], ah[mf][1], ah[mf][2], ah[mf][3], st + OFF_AH + o);
                LDSM4(al[mf][0], al[mf][1], al[mf][2], al[mf][3], st + OFF_AL + o);
            }
#pragma unroll
            for (int p = 0; p < 4; p++) {
                int r = warpN * 64 + p * 16 + (lane & 7) + ((lane >> 4) << 3);
                int c = ks * 2 + ((lane >> 3) & 1);
                uint32_t o = swz(r, c);
                LDSM4(bh[2 * p][0], bh[2 * p][1], bh[2 * p + 1][0], bh[2 * p + 1][1], st + OFF_BH + o);
                LDSM4(bl[2 * p][0], bl[2 * p][1], bl[2 * p + 1][0], bl[2 * p + 1][1], st + OFF_BL + o);
            }
#pragma unroll
            for (int mf = 0; mf < 2; mf++)
#pragma unroll
                for (int nf = 0; nf < 8; nf++) {
                    MMA16816(acc[mf][nf], ah[mf], bh[nf]);
                    MMA16816(acc[mf][nf], ah[mf], bl[nf]);
                    MMA16816(acc[mf][nf], al[mf], bh[nf]);
                }
        }
        if (i + 1 < nk) {
            uint32_t st2 = sb + (uint32_t)((i + 1) & 1) * 32768u;
            sts_half(st2 + OFF_AH, st2 + OFF_AL, lrow, lhalf * 2, fa);
            sts_half(st2 + OFF_BH, st2 + OFF_BL, lrow, lhalf * 2, fb);
            __syncthreads();
        }
    }

#pragma unroll
    for (int mf = 0; mf < 2; mf++)
#pragma unroll
        for (int nf = 0; nf < 8; nf++) {
            int m0 = bm + warpM * 32 + mf * 16 + (lane >> 2);
            int n = bn + warpN * 64 + nf * 8 + (lane & 3) * 2;
            float b0 = 0.f, b1 = 0.f;
            if (bias) { b0 = bias[n]; b1 = bias[n + 1]; }
#pragma unroll
            for (int hh = 0; hh < 2; hh++) {
                int m = m0 + hh * 8;
                float2 vv = make_float2(acc[mf][nf][2 * hh] + b0, acc[mf][nf][2 * hh + 1] + b1);
                *(float2*)(C + (size_t)m * ldc + n) = vv;
            }
        }
}

// ================= BM=64 mma GEMM (serial path) =================
#define MG64_SMEM (2 * 24576)
#define O64_AH 0u
#define O64_AL 4096u
#define O64_BH 8192u
#define O64_BL 16384u

__global__ __launch_bounds__(256, 1) void mmagemm64_kernel(
    const float* __restrict__ A0, const float* __restrict__ A1, int splitN, int lda0,
    const float* __restrict__ W, int ldw,
    const float* __restrict__ bias,
    const float* __restrict__ addmat, int ldadd,
    float* __restrict__ C, int ldc,
    int M, int N, int K, int act)
{
    extern __shared__ char dsm[];
    uint32_t sb = smem_u32(dsm);
    int tid = threadIdx.x, lane = tid & 31, wid = tid >> 5;
    int bm = blockIdx.y * 64, bn = blockIdx.x * 128;
    const float* __restrict__ A = (bn < splitN) ? A0 : A1;
    int warpM = wid & 1, warpN = wid >> 1;

    int lrow = tid >> 1, lhalf = tid & 1;
    int arow = (tid & 127) >> 1;
    bool doA = tid < 128;
    const float* rowA = A + (size_t)(bm + arow) * lda0 + lhalf * 16;
    const float* bp = W + (size_t)(bn + lrow) * ldw + lhalf * 16;

    float acc[2][4][4];
#pragma unroll
    for (int i = 0; i < 2; i++)
#pragma unroll
        for (int j = 0; j < 4; j++)
#pragma unroll
            for (int q = 0; q < 4; q++) acc[i][j][q] = 0.f;

    float fa[16], fb[16];
    int nk = K >> 5;

    {
        ldg16(bp, fb);
        if (doA) ldg16(rowA, fa);
        sts_half(sb + O64_BH, sb + O64_BL, lrow, lhalf * 2, fb);
        if (doA) sts_half(sb + O64_AH, sb + O64_AL, arow, lhalf * 2, fa);
    }
    __syncthreads();

    for (int i = 0; i < nk; i++) {
        if (i + 1 < nk) {
            int kk = (i + 1) * 32;
            ldg16(bp + kk, fb);
            if (doA) ldg16(rowA + kk, fa);
        }
        uint32_t st = sb + (uint32_t)(i & 1) * 24576u;
#pragma unroll
        for (int ks = 0; ks < 2; ks++) {
            uint32_t ah[2][4], al[2][4], bh[4][2], bl[4][2];
#pragma unroll
            for (int mf = 0; mf < 2; mf++) {
                int r = warpM * 32 + mf * 16 + (lane & 15);
                int c = ks * 2 + (lane >> 4);
                uint32_t o = swz(r, c);
                LDSM4(ah[mf][0], ah[mf][1], ah[mf][2], ah[mf][3], st + O64_AH + o);
                LDSM4(al[mf][0], al[mf][1], al[mf][2], al[mf][3], st + O64_AL + o);
            }
#pragma unroll
            for (int p = 0; p < 2; p++) {
                int r = warpN * 32 + p * 16 + (lane & 7) + ((lane >> 4) << 3);
                int c = ks * 2 + ((lane >> 3) & 1);
                uint32_t o = swz(r, c);
                LDSM4(bh[2 * p][0], bh[2 * p][1], bh[2 * p + 1][0], bh[2 * p + 1][1], st + O64_BH + o);
                LDSM4(bl[2 * p][0], bl[2 * p][1], bl[2 * p + 1][0], bl[2 * p + 1][1], st + O64_BL + o);
            }
#pragma unroll
            for (int mf = 0; mf < 2; mf++)
#pragma unroll
                for (int nf = 0; nf < 4; nf++) {
                    MMA16816(acc[mf][nf], ah[mf], bh[nf]);
                    MMA16816(acc[mf][nf], ah[mf], bl[nf]);
                    MMA16816(acc[mf][nf], al[mf], bh[nf]);
                }
        }
        if (i + 1 < nk) {
            uint32_t st2 = sb + (uint32_t)((i + 1) & 1) * 24576u;
            sts_half(st2 + O64_BH, st2 + O64_BL, lrow, lhalf * 2, fb);
            if (doA) sts_half(st2 + O64_AH, st2 + O64_AL, arow, lhalf * 2, fa);
            __syncthreads();
        }
    }

#pragma unroll
    for (int mf = 0; mf < 2; mf++)
#pragma unroll
        for (int nf = 0; nf < 4; nf++) {
            int m0 = bm + warpM * 32 + mf * 16 + (lane >> 2);
            int n = bn + warpN * 32 + nf * 8 + (lane & 3) * 2;
            float b0 = 0.f, b1 = 0.f;
            if (bias) { b0 = bias[n]; b1 = bias[n + 1]; }
#pragma unroll
            for (int hh = 0; hh < 2; hh++) {
                int m = m0 + hh * 8;
                float v0 = acc[mf][nf][2 * hh] + b0;
                float v1 = acc[mf][nf][2 * hh + 1] + b1;
                if (addmat) {
                    const float* am = addmat + (size_t)m * ldadd + n;
                    v0 += am[0]; v1 += am[1];
                }
                if (act == 1) { v0 = tanhf(v0); v1 = tanhf(v1); }
                float2 vv = make_float2(v0, v1);
                *(float2*)(C + (size_t)m * ldc + n) = vv;
            }
        }
}

// ---------------- SIMT fp32 GEMM (final output) ----------------
__global__ __launch_bounds__(256) void gemm_kernel(
    const float* __restrict__ A, const float* __restrict__ W, int ldw,
    const float* __restrict__ bias,
    float* __restrict__ C, int ldc,
    int M, int N, int K)
{
    __shared__ float As[16][64];
    __shared__ float Bs[16][64];
    int bn = blockIdx.x * 64;
    int bm = blockIdx.y * 64;

    int tid = threadIdx.x;
    int tx = tid & 15, ty = tid >> 4;
    int lr = tid >> 2;
    int lk = (tid & 3) * 4;

    float acc[4][4];
#pragma unroll
    for (int i = 0; i < 4; i++)
#pragma unroll
        for (int j = 0; j < 4; j++) acc[i][j] = 0.f;

    for (int k0 = 0; k0 < K; k0 += 16) {
        float4 a4 = *(const float4*)(A + (size_t)(bm + lr) * K + k0 + lk);
        As[lk + 0][lr] = a4.x; As[lk + 1][lr] = a4.y;
        As[lk + 2][lr] = a4.z; As[lk + 3][lr] = a4.w;
        float4 b4 = make_float4(0.f, 0.f, 0.f, 0.f);
        if (bn + lr < N)
            b4 = *(const float4*)(W + (size_t)(bn + lr) * ldw + k0 + lk);
        Bs[lk + 0][lr] = b4.x; Bs[lk + 1][lr] = b4.y;
        Bs[lk + 2][lr] = b4.z; Bs[lk + 3][lr] = b4.w;
        __syncthreads();
#pragma unroll
        for (int kk = 0; kk < 16; kk++) {
            float ra[4], rb[4];
#pragma unroll
            for (int i = 0; i < 4; i++) ra[i] = As[kk][ty * 4 + i];
#pragma unroll
            for (int j = 0; j < 4; j++) rb[j] = Bs[kk][tx * 4 + j];
#pragma unroll
            for (int i = 0; i < 4; i++)
#pragma unroll
                for (int j = 0; j < 4; j++) acc[i][j] += ra[i] * rb[j];
        }
        __syncthreads();
    }

#pragma unroll
    for (int i = 0; i < 4; i++) {
        int m = bm + ty * 4 + i;
#pragma unroll
        for (int j = 0; j < 4; j++) {
            int n = bn + tx * 4 + j;
            if (n < N)
                C[(size_t)m * ldc + n] = acc[i][j] + bias[n];
        }
    }
}

// ---------------- prep kernels ----------------
__global__ void pack_catpre_kernel(const float* __restrict__ px, const float* __restrict__ py,
                                   float* __restrict__ out)
{
    int idx = blockIdx.x * 256 + threadIdx.x;
    if (idx >= LPRE * B_ * 64) return;
    int c = idx & 63;
    int tb = idx >> 6;
    float v = 0.f;
    if (c < 32) v = px[(size_t)tb * 32 + c];
    else if (c < 48) v = py[(size_t)tb * 16 + (c - 32)];
    out[idx] = v;
}

__global__ void make_Mf_kernel(const float* __restrict__ Wih, const float* __restrict__ embW,
                               const float* __restrict__ embb, const float* __restrict__ bih,
                               float* __restrict__ Mf, float* __restrict__ gib)
{
    int idx = blockIdx.x * 256 + threadIdx.x;
    if (idx < G3_ * 64) {
        int i = idx >> 6, k = idx & 63;
        float s = 0.f;
        if (k < 48)
            for (int j = 0; j < H_; j++) s += Wih[(size_t)i * H_ + j] * embW[(size_t)j * 48 + k];
        Mf[idx] = s;
    } else if (idx < G3_ * 64 + G3_) {
        int i = idx - G3_ * 64;
        float s = bih[i];
        for (int j = 0; j < H_; j++) s += Wih[(size_t)i * H_ + j] * embb[j];
        gib[i] = s;
    }
}

__global__ void make_M1_kernel(const float* __restrict__ decEmbW, const float* __restrict__ decEmbb,
                               const float* __restrict__ outW, const float* __restrict__ outb,
                               float* __restrict__ M1, float* __restrict__ c1, float* __restrict__ c0fix)
{
    int idx = blockIdx.x * 256 + threadIdx.x;
    if (idx < H_ * H_) {
        int i = idx / H_, j = idx % H_;
        float s = 0.f;
        for (int k = 0; k < 16; k++) s += decEmbW[(size_t)i * 48 + k] * outW[(size_t)k * H_ + j];
        M1[idx] = s;
    } else if (idx < H_ * H_ + H_) {
        int i = idx - H_ * H_;
        float s = 0.f;
        for (int k = 0; k < 16; k++) s += decEmbW[(size_t)i * 48 + k] * outb[k];
        c1[i] = s + decEmbb[i];
        c0fix[i] = -s;
    }
}

__global__ void stack_copy_kernel(const float* __restrict__ Wih, const float* __restrict__ Whh,
                                  const float* __restrict__ bih, const float* __restrict__ bhh,
                                  float* __restrict__ Wst, float* __restrict__ bst)
{
    int idx = blockIdx.x * 256 + threadIdx.x;
    if (idx < G3_ * H_) {
        Wst[idx] = Wih[idx];
        Wst[G3_ * H_ + idx] = Whh[idx];
    }
    if (idx < G3_) { bst[idx] = bih[idx]; bst[G3_ + idx] = bhh[idx]; }
}

__global__ void zero_h_kernel(float* __restrict__ h)
{
    int idx = blockIdx.x * 256 + threadIdx.x;
    if (idx < B_ * H_) h[idx] = 0.f;
}

// attn prep: W2 rows 0-127 (Wfuse), WexC rows 0-127 (We), bias384[0:128), Wh_pad, corr_l
__global__ void make_attnprep_kernel(const float* __restrict__ attnW, const float* __restrict__ attnb,
                                     const float* __restrict__ M1, const float* __restrict__ c0fix,
                                     float* __restrict__ WexC, float* __restrict__ Wh_pad,
                                     float* __restrict__ W2, float* __restrict__ bias384,
                                     float* __restrict__ corr_l)
{
    int idx = blockIdx.x * 256 + threadIdx.x;
    if (idx >= 128 * H_) return;
    int m = idx >> 8, k = idx & 255;
    float we = 0.f, wh = 0.f, wf = 0.f;
    if (m < ML_) {
        we = attnW[(size_t)m * 512 + k];
        wh = attnW[(size_t)m * 512 + 256 + k];
        float s = wh;
        for (int j = 0; j < H_; j++) s += attnW[(size_t)m * 512 + j] * M1[(size_t)j * H_ + k];
        wf = s;
    }
    WexC[idx] = we; Wh_pad[idx] = wh; W2[idx] = wf;
    if (k == 0) {
        float ab = 0.f, cl = 0.f;
        if (m < ML_) {
            ab = attnb[m];
            for (int j = 0; j < H_; j++) cl += c0fix[j] * attnW[(size_t)m * 512 + j];
        }
        bias384[m] = ab;
        corr_l[m] = cl;
    }
}

// comb prep: W2 rows 128-383 (Wch = combW_e*M1), WexC rows 128-383 (combW_e),
// bias384[128:384) = comb_b, corr_c = combW_e . c0fix
__global__ void make_combprep_kernel(const float* __restrict__ combW, const float* __restrict__ combb,
                                     const float* __restrict__ M1, const float* __restrict__ c0fix,
                                     float* __restrict__ WexC, float* __restrict__ W2,
                                     float* __restrict__ bias384, float* __restrict__ corr_c)
{
    int idx = blockIdx.x * 256 + threadIdx.x;
    if (idx >= H_ * H_) return;
    int n = idx >> 8, k = idx & 255;
    float s = 0.f;
    for (int j = 0; j < H_; j++) s += combW[(size_t)n * 512 + j] * M1[(size_t)j * H_ + k];
    W2[(size_t)(128 + n) * H_ + k] = s;
    WexC[(size_t)(128 + n) * H_ + k] = combW[(size_t)n * 512 + k];
    if (k == 0) {
        bias384[128 + n] = combb[n];
        float cc = 0.f;
        for (int j = 0; j < H_; j++) cc += combW[(size_t)n * 512 + j] * c0fix[j];
        corr_c[n] = cc;
    }
}

// ---------------- GRU gates ----------------
__global__ __launch_bounds__(256) void gates_kernel(
    const float* __restrict__ gi, int ldgi,
    const float* __restrict__ gh, int ldgh,
    const float* __restrict__ h,
    float* __restrict__ h2, float* __restrict__ out2)
{
    int idx = blockIdx.x * 256 + threadIdx.x;
    int b = idx >> 8, j = idx & 255;
    const float* gib = gi + (size_t)b * ldgi;
    const float* ghb = gh + (size_t)b * ldgh;
    float v = gru1(gib[j], gib[256 + j], gib[512 + j],
                   ghb[j], ghb[256 + j], ghb[512 + j], h[idx]);
    h2[idx] = v;
    if (out2) out2[idx] = v;
}

// ---------------- softmax + context ----------------
__global__ __launch_bounds__(256) void smctx_kernel(
    const float* __restrict__ logits, int ldl,
    const float* __restrict__ ENC,
    float* __restrict__ ctx)
{
    int b = blockIdx.x;
    __shared__ float saw[ML_];
    int tid = threadIdx.x;

    if (tid < 32) {
        const float* lb = logits + (size_t)b * ldl;
        float x0 = lb[tid], x1 = lb[tid + 32];
        float x2 = (tid < 16) ? lb[tid + 64] : -1e30f;
        float mx = fmaxf(x0, fmaxf(x1, x2));
#pragma unroll
        for (int o = 16; o; o >>= 1) mx = fmaxf(mx, __shfl_xor_sync(0xffffffffu, mx, o));
        float e0 = expf(x0 - mx), e1 = expf(x1 - mx);
        float e2 = (tid < 16) ? expf(x2 - mx) : 0.f;
        float s = e0 + e1 + e2;
#pragma unroll
        for (int o = 16; o; o >>= 1) s += __shfl_xor_sync(0xffffffffu, s, o);
        float inv = 1.f / s;
        saw[tid] = e0 * inv;
        saw[tid + 32] = e1 * inv;
        if (tid < 16) saw[tid + 64] = e2 * inv;
    }
    __syncthreads();

    float acc = 0.f;
    const float* encb = ENC + (size_t)b * 256 + tid;
#pragma unroll 4
    for (int m = 0; m < LPRE; m++) acc += saw[m] * encb[(size_t)m * B_ * 256];
    ctx[(size_t)b * 256 + tid] = acc;
}

// ---------------- host launcher ----------------
static inline void run_mma(const float* A, int lda, const float* W, int ldw,
                           const float* bias, float* C, int ldc, int M, int N, int K)
{
    dim3 grid(N / 128, M / 128);
    mmagemm_kernel<<<grid, 256, MG_SMEM>>>(A, lda, W, ldw, bias, C, ldc, M, N, K);
}

static inline void run_mma64(const float* A0, const float* A1, int splitN, int lda0,
                             const float* W, int ldw, const float* bias,
                             const float* addmat, int ldadd,
                             float* C, int ldc, int M, int N, int K, int act)
{
    dim3 grid(N / 128, M / 64);
    mmagemm64_kernel<<<grid, 256, MG64_SMEM>>>(A0, A1, splitN, lda0, W, ldw, bias,
                                               addmat, ldadd, C, ldc, M, N, K, act);
}

extern "C" void kernel_launch(void* const* d_in, const int* in_sizes, int n_in,
                              void* d_out, int out_size)
{
    const float* pre_x    = (const float*)d_in[0];
    const float* pre_y    = (const float*)d_in[1];
    const float* fwd_x    = (const float*)d_in[2];
    const float* encEmbW  = (const float*)d_in[3];
    const float* encEmbB  = (const float*)d_in[4];
    const float* encWih   = (const float*)d_in[5];
    const float* encWhh   = (const float*)d_in[6];
    const float* encBih   = (const float*)d_in[7];
    const float* encBhh   = (const float*)d_in[8];
    const float* decEmbW  = (const float*)d_in[9];
    const float* decEmbB  = (const float*)d_in[10];
    const float* attnW    = (const float*)d_in[11];
    const float* attnB    = (const float*)d_in[12];
    const float* combW    = (const float*)d_in[13];
    const float* combB    = (const float*)d_in[14];
    const float* decWih   = (const float*)d_in[15];
    const float* decWhh   = (const float*)d_in[16];
    const float* decBih   = (const float*)d_in[17];
    const float* decBhh   = (const float*)d_in[18];
    const float* outW     = (const float*)d_in[19];
    const float* outB     = (const float*)d_in[20];
    float* out = (float*)d_out;

    cudaFuncSetAttribute(mmagemm_kernel, cudaFuncAttributeMaxDynamicSharedMemorySize, MG_SMEM);
    cudaFuncSetAttribute(mmagemm64_kernel, cudaFuncAttributeMaxDynamicSharedMemorySize, MG64_SMEM);

    float *catpre, *Mf, *gibias, *GIenc, *ENC, *M1, *c1, *c0fix, *Xe;
    float *Wstack, *bstack, *ctx, *lp, *gbuf, *gigh, *ghb, *hb0, *hb1, *Hall;
    float *Wh_pad, *W2, *WexC, *bias384, *corr_l, *corr_c, *XLC;
    cudaGetSymbolAddress((void**)&catpre, g_catpre64);
    cudaGetSymbolAddress((void**)&Mf, g_Mf64);
    cudaGetSymbolAddress((void**)&gibias, g_gibias);
    cudaGetSymbolAddress((void**)&GIenc, g_GIenc);
    cudaGetSymbolAddress((void**)&ENC, g_ENC);
    cudaGetSymbolAddress((void**)&M1, g_M1);
    cudaGetSymbolAddress((void**)&c1, g_c1);
    cudaGetSymbolAddress((void**)&c0fix, g_c0fix);
    cudaGetSymbolAddress((void**)&Xe, g_Xe);
    cudaGetSymbolAddress((void**)&Wstack, g_Wstack);
    cudaGetSymbolAddress((void**)&bstack, g_bstack);
    cudaGetSymbolAddress((void**)&ctx, g_ctx);
    cudaGetSymbolAddress((void**)&lp, g_lp);
    cudaGetSymbolAddress((void**)&gbuf, g_g);
    cudaGetSymbolAddress((void**)&gigh, g_gigh);
    cudaGetSymbolAddress((void**)&ghb, g_gh);
    cudaGetSymbolAddress((void**)&hb0, g_hbuf);
    hb1 = hb0 + B_ * H_;
    cudaGetSymbolAddress((void**)&Hall, g_Hall);
    cudaGetSymbolAddress((void**)&Wh_pad, g_Wh_pad);
    cudaGetSymbolAddress((void**)&W2, g_W2);
    cudaGetSymbolAddress((void**)&WexC, g_WexC);
    cudaGetSymbolAddress((void**)&bias384, g_bias384);
    cudaGetSymbolAddress((void**)&corr_l, g_corr_l);
    cudaGetSymbolAddress((void**)&corr_c, g_corr_c);
    cudaGetSymbolAddress((void**)&XLC, g_XLC);

    float* hb[2] = {hb0, hb1};

    // ---- prep ----
    pack_catpre_kernel<<<(LPRE * B_ * 64 + 255) / 256, 256>>>(pre_x, pre_y, catpre);
    make_Mf_kernel<<<(G3_ * 64 + G3_ + 255) / 256, 256>>>(encWih, encEmbW, encEmbB, encBih, Mf, gibias);
    make_M1_kernel<<<(H_ * H_ + H_ + 255) / 256, 256>>>(decEmbW, decEmbB, outW, outB, M1, c1, c0fix);
    stack_copy_kernel<<<(G3_ * H_ + 255) / 256, 256>>>(decWih, decWhh, decBih, decBhh, Wstack, bstack);
    zero_h_kernel<<<(B_ * H_ + 255) / 256, 256>>>(hb[0]);
    make_attnprep_kernel<<<(128 * H_ + 255) / 256, 256>>>(attnW, attnB, M1, c0fix,
                                                          WexC, Wh_pad, W2, bias384, corr_l);
    make_combprep_kernel<<<(H_ * H_ + 255) / 256, 256>>>(combW, combB, M1, c0fix,
                                                         WexC, W2, bias384, corr_c);

    // ---- prework GEMMs ----
    run_mma(catpre, 64, Mf, 64, gibias, GIenc, G3_, LPRE * B_, G3_, 64);
    {
        dim3 grid(H_ / 128, (LFWD * B_) / 128);
        mmagemm_kernel<<<grid, 256, MG_SMEM>>>(fwd_x, 32, decEmbW + 16, 48, c1, Xe, H_, LFWD * B_, H_, 32);
    }
    // XLC = Xe @ WexC^T + bias384  [80*1024, 384]
    run_mma(Xe, 256, WexC, 256, bias384, XLC, 384, LFWD * B_, 384, 256);

    // ---- encoder: 60 steps ----
    int cur = 0;
    for (int t = 0; t < LPRE; t++) {
        run_mma64(hb[cur], hb[cur], 1 << 30, 256,
                  encWhh, H_, encBhh, nullptr, 0, ghb, G3_, B_, G3_, H_, 0);
        gates_kernel<<<B_, 256>>>(GIenc + (size_t)t * B_ * G3_, G3_, ghb, G3_,
                                  hb[cur], hb[cur ^ 1], ENC + (size_t)t * B_ * H_);
        cur ^= 1;
    }

    // ---- decoder: 80 steps, 5 kernels each ----
    for (int t = 0; t < LFWD; t++) {
        if (t == 0) {
            // logits only: h@Wh_pad + XLC[0][:,0:128] + corr_l -> lp cols 0-127
            run_mma64(hb[cur], hb[cur], 1 << 30, 256,
                      Wh_pad, 256, corr_l, XLC, 384, lp, 384, B_, 128, 256, 0);
        } else {
            // [logits|pre] = h@W2^T + XLC[t]
            run_mma64(hb[cur], hb[cur], 1 << 30, 256,
                      W2, 256, nullptr, XLC + (size_t)t * B_ * 384, 384,
                      lp, 384, B_, 384, 256, 0);
        }
        smctx_kernel<<<B_, 256>>>(lp, 384, ENC, ctx);
        if (t == 0) {
            // g = tanh(ctx@combW_c + (XLC[0][:,128:] = XC0+comb_b) + corr_c)
            run_mma64(ctx, ctx, 1 << 30, 256,
                      combW + 256, 512, corr_c, XLC + 128, 384, gbuf, H_, B_, H_, 256, 1);
        } else {
            // g = tanh(ctx@combW_c + pre)
            run_mma64(ctx, ctx, 1 << 30, 256,
                      combW + 256, 512, nullptr, lp + 128, 384, gbuf, H_, B_, H_, 256, 1);
        }
        // gigh = [g|h] @ Wstack   (192 blocks)
        run_mma64(gbuf, hb[cur], G3_, 256,
                  Wstack, H_, bstack, nullptr, 0, gigh, 2 * G3_, B_, 2 * G3_, H_, 0);
        gates_kernel<<<B_, 256>>>(gigh, 2 * G3_, gigh + G3_, 2 * G3_,
                                  hb[cur], hb[cur ^ 1], Hall + (size_t)t * B_ * H_);
        cur ^= 1;
    }

    // ---- final outputs: ys = Hall @ out_W.T + out_b ----
    {
        dim3 grid(1, (LFWD * B_) / 64);
        gemm_kernel<<<grid, 256>>>(Hall, outW, H_, outB, out, 16, LFWD * B_, 16, H_);
    }
}